// round 6
// baseline (speedup 1.0000x reference)
#include <cuda_runtime.h>

#define NUM_ENT 50000
#define NUM_REL 237
#define REXT    238
#define D       64
#define BN_EPS  1e-5f

#define NT_ROWS 64
#define NT_PAD  68
#define NT_SMEM (2 * 192 * NT_PAD * 4)   // 104.4 KB

// ---------------- device scratch ----------------
__device__ float g_SO[NUM_ENT * D];
__device__ float g_SI[NUM_ENT * D];
__device__ float g_ntmp[NUM_ENT * D];
__device__ float g_nbuf[NUM_ENT * D];
__device__ float g_rext[REXT * D];
__device__ float g_rnext[NUM_REL * D];
__device__ float g_sum[D], g_sumsq[D];
__device__ float g_scale[D], g_shift[D];

// ---- f32x2 packed helpers ----
__device__ __forceinline__ void fma2(unsigned long long& d,
                                     unsigned long long a,
                                     unsigned long long b) {
    asm("fma.rn.f32x2 %0, %1, %2, %0;" : "+l"(d) : "l"(a), "l"(b));
}
__device__ __forceinline__ unsigned long long pack2(float lo, float hi) {
    unsigned long long p;
    asm("mov.b64 %0, {%1, %2};" : "=l"(p) : "f"(lo), "f"(hi));
    return p;
}
__device__ __forceinline__ void unpack2(unsigned long long p, float& lo, float& hi) {
    asm("mov.b64 {%0, %1}, %2;" : "=f"(lo), "=f"(hi) : "l"(p));
}

// ---------------- prep: zero scatter buffers + stats + build r_ext ----------------
__global__ void prep_kernel(const float* __restrict__ r_in,
                            const float* __restrict__ loop_rel, int layer) {
    const int n4 = NUM_ENT * D / 4;
    float4 z = make_float4(0.f, 0.f, 0.f, 0.f);
    int stride = gridDim.x * blockDim.x;
    int tid0 = blockIdx.x * blockDim.x + threadIdx.x;
    for (int i = tid0; i < n4; i += stride) {
        reinterpret_cast<float4*>(g_SO)[i] = z;
        reinterpret_cast<float4*>(g_SI)[i] = z;
    }
    if (tid0 < D) { g_sum[tid0] = 0.f; g_sumsq[tid0] = 0.f; }
    const float* r = layer ? g_rnext : r_in;
    for (int i = tid0; i < REXT * D; i += stride) {
        g_rext[i] = (i < NUM_REL * D) ? r[i] : loop_rel[i - NUM_REL * D];
    }
}

// ---------------- edge scatter ----------------
__global__ __launch_bounds__(256) void edge_scatter(
    const float* __restrict__ nfeat_in0,
    const int*   __restrict__ src,
    const int*   __restrict__ dst,
    const int*   __restrict__ etype,
    const int*   __restrict__ mask,
    const float* __restrict__ norm,
    int E, int layer)
{
    const float* __restrict__ nf = layer ? g_nbuf : nfeat_in0;
    int gid = blockIdx.x * blockDim.x + threadIdx.x;
    int e = gid >> 4;
    if (e >= E) return;
    int c = (gid & 15) * 4;

    int s  = __ldg(src + e);
    int d  = __ldg(dst + e);
    int t  = __ldg(etype + e);
    int m  = __ldg(mask + e);
    float nm = __ldg(norm + e);

    float4 nv = __ldg(reinterpret_cast<const float4*>(nf + s * D + c));
    float4 rv = __ldg(reinterpret_cast<const float4*>(g_rext + t * D + c));

    float4 cm;
    cm.x = nv.x * rv.x * nm;
    cm.y = nv.y * rv.y * nm;
    cm.z = nv.z * rv.z * nm;
    cm.w = nv.w * rv.w * nm;

    float* base = (m ? g_SO : g_SI) + (size_t)d * D + c;
    asm volatile("red.global.add.v4.f32 [%0], {%1,%2,%3,%4};"
                 :: "l"(base), "f"(cm.x), "f"(cm.y), "f"(cm.z), "f"(cm.w)
                 : "memory");
}

// ---------------- node transform: tiled GEMM w/ packed f32x2 FMA ----------------
// Block 64 rows x 64 cols, 256 threads; thread = 4 rows (2 f32x2 pairs) x 4 cols.
__global__ __launch_bounds__(256) void node_transform(
    const float* __restrict__ nfeat_in0,
    const float* __restrict__ WS, const float* __restrict__ WO,
    const float* __restrict__ WI, const float* __restrict__ LR,
    int rows, int layer)
{
    extern __shared__ float smem[];
    float* sW = smem;                 // [192][NT_PAD]
    float* sX = smem + 192 * NT_PAD;  // [192][NT_PAD]

    const float* __restrict__ nf = layer ? g_nbuf : nfeat_in0;
    const int tid = threadIdx.x;       // 256 threads
    const int tr  = tid >> 4;          // 0..15 -> rows tr*4..tr*4+3
    const int tc  = tid & 15;          // 0..15 -> cols tc*4..tc*4+3
    const int row0 = blockIdx.x * NT_ROWS;
    const float third = 1.0f / 3.0f;

    // ---- stage W (fused lr & 1/3), transposed to [k][c] ----
    const float* wsrc[3] = {WS, WO, WI};
#pragma unroll
    for (int s = 0; s < 3; s++) {
        for (int i4 = tid; i4 < 1024; i4 += 256) {
            int c  = i4 >> 4;
            int k4 = (i4 & 15) * 4;
            float4 w = __ldg(reinterpret_cast<const float4*>(wsrc[s] + c * D + k4));
            float m0 = third, m1 = third, m2 = third, m3 = third;
            if (s == 0) {
                m0 *= __ldg(LR + k4);     m1 *= __ldg(LR + k4 + 1);
                m2 *= __ldg(LR + k4 + 2); m3 *= __ldg(LR + k4 + 3);
            }
            int kb = s * 64 + k4;
            sW[(kb + 0) * NT_PAD + c] = w.x * m0;
            sW[(kb + 1) * NT_PAD + c] = w.y * m1;
            sW[(kb + 2) * NT_PAD + c] = w.z * m2;
            sW[(kb + 3) * NT_PAD + c] = w.w * m3;
        }
    }

    // ---- stage X transposed to [k][row] ----
    const float* xsrc[3] = {nf, g_SO, g_SI};
#pragma unroll
    for (int s = 0; s < 3; s++) {
        for (int i4 = tid; i4 < 1024; i4 += 256) {
            int row = i4 >> 4;
            int k4  = (i4 & 15) * 4;
            int grow = row0 + row;
            float4 v = make_float4(0.f, 0.f, 0.f, 0.f);
            if (grow < rows)
                v = __ldg(reinterpret_cast<const float4*>(xsrc[s] + (size_t)grow * D + k4));
            int kb = s * 64 + k4;
            sX[(kb + 0) * NT_PAD + row] = v.x;
            sX[(kb + 1) * NT_PAD + row] = v.y;
            sX[(kb + 2) * NT_PAD + row] = v.z;
            sX[(kb + 3) * NT_PAD + row] = v.w;
        }
    }
    __syncthreads();

    // ---- main loop: acc2[rp][c], rp = row-pair within the 4-row tile ----
    unsigned long long acc2[2][4];
#pragma unroll
    for (int rp = 0; rp < 2; rp++)
#pragma unroll
        for (int c = 0; c < 4; c++) acc2[rp][c] = 0ULL;

    const float* xbase = sX + tr * 4;
    const float* wbase = sW + tc * 4;

#pragma unroll 6
    for (int k = 0; k < 192; k++) {
        float4 xv = *reinterpret_cast<const float4*>(xbase + k * NT_PAD);
        float4 wv = *reinterpret_cast<const float4*>(wbase + k * NT_PAD);

        unsigned long long xp0 = pack2(xv.x, xv.y);
        unsigned long long xp1 = pack2(xv.z, xv.w);

        unsigned long long wd0 = pack2(wv.x, wv.x);
        unsigned long long wd1 = pack2(wv.y, wv.y);
        unsigned long long wd2 = pack2(wv.z, wv.z);
        unsigned long long wd3 = pack2(wv.w, wv.w);

        fma2(acc2[0][0], xp0, wd0); fma2(acc2[0][1], xp0, wd1);
        fma2(acc2[0][2], xp0, wd2); fma2(acc2[0][3], xp0, wd3);
        fma2(acc2[1][0], xp1, wd0); fma2(acc2[1][1], xp1, wd1);
        fma2(acc2[1][2], xp1, wd2); fma2(acc2[1][3], xp1, wd3);
    }

    // ---- store + per-thread BN partial stats ----
    const int woff = tc * 4;
    float s_[4] = {0.f, 0.f, 0.f, 0.f};
    float q_[4] = {0.f, 0.f, 0.f, 0.f};
#pragma unroll
    for (int rp = 0; rp < 2; rp++) {
        float lo[4], hi[4];
#pragma unroll
        for (int c = 0; c < 4; c++) unpack2(acc2[rp][c], lo[c], hi[c]);
        int r0g = row0 + tr * 4 + rp * 2;
        if (r0g < rows) {
            float4 o; o.x = lo[0]; o.y = lo[1]; o.z = lo[2]; o.w = lo[3];
            *reinterpret_cast<float4*>(g_ntmp + (size_t)r0g * D + woff) = o;
#pragma unroll
            for (int c = 0; c < 4; c++) { s_[c] += lo[c]; q_[c] += lo[c] * lo[c]; }
        }
        if (r0g + 1 < rows) {
            float4 o; o.x = hi[0]; o.y = hi[1]; o.z = hi[2]; o.w = hi[3];
            *reinterpret_cast<float4*>(g_ntmp + (size_t)(r0g + 1) * D + woff) = o;
#pragma unroll
            for (int c = 0; c < 4; c++) { s_[c] += hi[c]; q_[c] += hi[c] * hi[c]; }
        }
    }

    // ---- block reduce stats (reuse sX region) ----
    __syncthreads();
    float* redS = sX;          // [64 cols][16 tr]
    float* redQ = sX + 1024;
#pragma unroll
    for (int c = 0; c < 4; c++) {
        redS[(woff + c) * 16 + tr] = s_[c];
        redQ[(woff + c) * 16 + tr] = q_[c];
    }
    __syncthreads();
    if (tid < D) {
        float ss = 0.f, qq = 0.f;
#pragma unroll
        for (int t = 0; t < 16; t++) {
            ss += redS[tid * 16 + t];
            qq += redQ[tid * 16 + t];
        }
        atomicAdd(&g_sum[tid],   ss);
        atomicAdd(&g_sumsq[tid], qq);
    }
}

// ---------------- BN finalize ----------------
__global__ void bn_finalize(const float* __restrict__ gamma,
                            const float* __restrict__ beta, int N) {
    int j = threadIdx.x;
    if (j >= D) return;
    float invN = 1.0f / (float)N;
    float mean = g_sum[j] * invN;
    float var  = fmaxf(g_sumsq[j] * invN - mean * mean, 0.f);
    float rstd = rsqrtf(var + BN_EPS);
    float g = __ldg(gamma + j);
    g_scale[j] = rstd * g;
    g_shift[j] = __ldg(beta + j) - mean * rstd * g;
}

// ---------------- finish: BN apply + tanh (blocks 0..NB-1) | rel update (rest) ----------------
#define BNA_BLOCKS ((NUM_ENT * D / 4 + 255) / 256)
__global__ __launch_bounds__(256) void finish_kernel(float* __restrict__ out_n,
                                                     const float* __restrict__ WR,
                                                     float* __restrict__ out_r,
                                                     int layer) {
    if (blockIdx.x < BNA_BLOCKS) {
        int i = blockIdx.x * 256 + threadIdx.x;
        const int n4 = NUM_ENT * D / 4;
        if (i >= n4) return;
        float* dst = layer ? out_n : g_nbuf;
        int col = (i & 15) * 4;
        float4 x  = reinterpret_cast<const float4*>(g_ntmp)[i];
        float4 sc = *reinterpret_cast<const float4*>(g_scale + col);
        float4 sh = *reinterpret_cast<const float4*>(g_shift + col);
        float4 y;
        y.x = tanhf(x.x * sc.x + sh.x);
        y.y = tanhf(x.y * sc.y + sh.y);
        y.z = tanhf(x.z * sc.z + sh.z);
        y.w = tanhf(x.w * sc.w + sh.w);
        reinterpret_cast<float4*>(dst)[i] = y;
    } else {
        int g = (blockIdx.x - BNA_BLOCKS) * 256 + threadIdx.x;
        int t = g >> 5;
        if (t >= NUM_REL) return;
        int lane = g & 31;
        int j0 = lane * 2;
        float* dst = layer ? out_r : g_rnext;
        float a0 = 0.f, a1 = 0.f;
#pragma unroll 8
        for (int k = 0; k < D; k++) {
            float v = g_rext[t * D + k];
            a0 += v * __ldg(WR + j0 * D + k);
            a1 += v * __ldg(WR + (j0 + 1) * D + k);
        }
        dst[t * D + j0]     = a0;
        dst[t * D + j0 + 1] = a1;
    }
}

// ---------------- launch ----------------
extern "C" void kernel_launch(void* const* d_in, const int* in_sizes, int n_in,
                              void* d_out, int out_size) {
    const float* n0   = (const float*)d_in[0];
    const float* r0   = (const float*)d_in[1];
    const float* norm = (const float*)d_in[2];
    const int*   src  = (const int*)d_in[3];
    const int*   dst  = (const int*)d_in[4];
    const int*   et   = (const int*)d_in[5];
    const int*   msk  = (const int*)d_in[6];
    const int E    = in_sizes[3];
    const int rows = in_sizes[0] / D;

    float* out   = (float*)d_out;
    float* out_n = out;
    float* out_r = out + (size_t)NUM_ENT * D;

    // idempotent; safe to call every time (also safe under graph capture:
    // first call happens on the pre-capture correctness run)
    cudaFuncSetAttribute(node_transform,
                         cudaFuncAttributeMaxDynamicSharedMemorySize, NT_SMEM);

    const int nt_blocks = (rows + NT_ROWS - 1) / NT_ROWS;
    const int fin_blocks = BNA_BLOCKS + (NUM_REL * 32 + 255) / 256;

    for (int l = 0; l < 2; l++) {
        const float* WO = (const float*)d_in[7  + 7 * l];
        const float* WI = (const float*)d_in[8  + 7 * l];
        const float* WS = (const float*)d_in[9  + 7 * l];
        const float* WR = (const float*)d_in[10 + 7 * l];
        const float* LR = (const float*)d_in[11 + 7 * l];
        const float* GA = (const float*)d_in[12 + 7 * l];
        const float* BE = (const float*)d_in[13 + 7 * l];

        prep_kernel<<<512, 256>>>(r0, LR, l);
        {
            long long threads = (long long)E * 16;
            int blocks = (int)((threads + 255) / 256);
            edge_scatter<<<blocks, 256>>>(n0, src, dst, et, msk, norm, E, l);
        }
        node_transform<<<nt_blocks, 256, NT_SMEM>>>(n0, WS, WO, WI, LR, rows, l);
        bn_finalize<<<1, 64>>>(GA, BE, rows);
        finish_kernel<<<fin_blocks, 256>>>(out_n, WR, out_r, l);
    }
}